// round 1
// baseline (speedup 1.0000x reference)
#include <cuda_runtime.h>
#include <cstdint>

// Problem constants (fixed by the reference setup_inputs)
static constexpr int Nn   = 100000;   // nodes
static constexpr int Ee   = 1600000;  // directed edges
static constexpr int IN_C = 128;
static constexpr int HID  = 64;
static constexpr int LAT  = 32;

// ---------------- device scratch (no allocations allowed) ----------------
__device__ __align__(16) float g_dinv[Nn];
__device__ int                 g_degi[Nn];
__device__ __align__(16) float g_norm[Ee];
__device__ __align__(16) float g_h  [(size_t)Nn * HID];  // h0 = x@W_in + b_in
__device__ __align__(16) float g_hw [(size_t)Nn * HID];  // h@W (also reused at width 32)
__device__ __align__(16) float g_acc[(size_t)Nn * HID];  // aggregation output / next h (pre-activation)
__device__ __align__(16) float g_lat[(size_t)Nn * LAT];  // skip-projection accumulator

// ---------------- helpers ----------------
__device__ __forceinline__ float leaky(float v) { return v > 0.f ? v : 0.2f * v; }

__device__ __forceinline__ void red4(float* p, float a, float b, float c, float d) {
    asm volatile("red.global.add.v4.f32 [%0], {%1,%2,%3,%4};"
                 :: "l"(p), "f"(a), "f"(b), "f"(c), "f"(d) : "memory");
}

// ---------------- degree / norm ----------------
__global__ void k_deg_init() {
    int i = blockIdx.x * blockDim.x + threadIdx.x;
    if (i < Nn) g_degi[i] = 1;  // self loop
}
__global__ void k_deg_count(const int* __restrict__ dst) {
    int e = blockIdx.x * blockDim.x + threadIdx.x;
    if (e < Ee) atomicAdd(&g_degi[dst[e]], 1);
}
__global__ void k_dinv() {
    int i = blockIdx.x * blockDim.x + threadIdx.x;
    if (i < Nn) g_dinv[i] = rsqrtf((float)g_degi[i]);
}
__global__ void k_norm(const int* __restrict__ src, const int* __restrict__ dst) {
    int e = blockIdx.x * blockDim.x + threadIdx.x;
    if (e < Ee) g_norm[e] = g_dinv[src[e]] * g_dinv[dst[e]];
}

// ---------------- tiled fp32 GEMM: out[N,COLS] = f(H)[N,K] @ W[K,COLS] (+bias) (+=) ----
template<int K, int COLS, int R, int PADK, bool LEAKY, bool ADD_BIAS, bool ACCUM>
__global__ __launch_bounds__(256) void k_gemm(const float* __restrict__ H,
                                              const float* __restrict__ W,
                                              const float* __restrict__ bias,
                                              float* __restrict__ out, int nrows)
{
    constexpr int CG     = COLS / 4;       // 4-col groups
    constexpr int GROUPS = 256 / CG;
    constexpr int RPT    = R / GROUPS;     // rows per thread
    __shared__ float Hs[R * PADK];
    __shared__ float Wsh[K * COLS];

    const int tid  = threadIdx.x;
    const int row0 = blockIdx.x * R;

    // load H tile (coalesced float4), applying leaky on read
    constexpr int NV = R * K / 4;
    #pragma unroll
    for (int i = tid; i < NV; i += 256) {
        int r  = i / (K / 4);
        int k4 = i % (K / 4);
        float4 v = make_float4(0.f, 0.f, 0.f, 0.f);
        if (row0 + r < nrows)
            v = *(const float4*)(H + (size_t)(row0 + r) * K + k4 * 4);
        if (LEAKY) { v.x = leaky(v.x); v.y = leaky(v.y); v.z = leaky(v.z); v.w = leaky(v.w); }
        float* dp = &Hs[r * PADK + k4 * 4];
        if (PADK % 4 == 0) { *(float4*)dp = v; }
        else { dp[0] = v.x; dp[1] = v.y; dp[2] = v.z; dp[3] = v.w; }
    }
    // load W tile
    #pragma unroll
    for (int i = tid; i < K * COLS / 4; i += 256)
        *(float4*)&Wsh[i * 4] = *(const float4*)(W + i * 4);
    __syncthreads();

    const int cg    = tid % CG;
    const int rbase = (tid / CG) * RPT;

    float acc[RPT][4];
    #pragma unroll
    for (int i = 0; i < RPT; i++) { acc[i][0] = acc[i][1] = acc[i][2] = acc[i][3] = 0.f; }

    #pragma unroll 8
    for (int k = 0; k < K; k++) {
        float4 w = *(float4*)&Wsh[k * COLS + cg * 4];
        #pragma unroll
        for (int i = 0; i < RPT; i++) {
            float a = Hs[(rbase + i) * PADK + k];
            acc[i][0] += a * w.x; acc[i][1] += a * w.y;
            acc[i][2] += a * w.z; acc[i][3] += a * w.w;
        }
    }

    float4 b = make_float4(0.f, 0.f, 0.f, 0.f);
    if (ADD_BIAS) b = *(const float4*)(bias + cg * 4);
    #pragma unroll
    for (int i = 0; i < RPT; i++) {
        int r = row0 + rbase + i;
        if (r < nrows) {
            float4 res = make_float4(acc[i][0] + b.x, acc[i][1] + b.y,
                                     acc[i][2] + b.z, acc[i][3] + b.w);
            float* op = out + (size_t)r * COLS + cg * 4;
            if (ACCUM) {
                float4 o = *(float4*)op;
                res.x += o.x; res.y += o.y; res.z += o.z; res.w += o.w;
            }
            *(float4*)op = res;
        }
    }
}

// ---------------- elementwise inits ----------------
// acc[v,:] = bg + hw[v,:] * dinv[v]^2   (self-loop + bias)
__global__ void k_init_acc(const float* __restrict__ hw, const float* __restrict__ bg) {
    int idx = blockIdx.x * blockDim.x + threadIdx.x;   // Nn*16 threads
    int v = idx >> 4, c4 = (idx & 15) * 4;
    float di = g_dinv[v]; float s = di * di;
    float4 h = *(const float4*)&hw[(size_t)v * HID + c4];
    float4 b = *(const float4*)&bg[c4];
    float4 r = make_float4(b.x + h.x * s, b.y + h.y * s, b.z + h.z * s, b.w + h.w * s);
    *(float4*)&g_acc[(size_t)v * HID + c4] = r;
}

// out[v,:] = lat[v,:] + hw32[v,:]*dinv^2 + (bl + bs0 + bs1 + bs2)
__global__ void k_out_init(const float* __restrict__ hw32,
                           const float* __restrict__ bl,
                           const float* __restrict__ bs,
                           float* __restrict__ out) {
    int idx = blockIdx.x * blockDim.x + threadIdx.x;   // Nn*8 threads
    int v = idx >> 3, c4 = (idx & 7) * 4;
    float di = g_dinv[v]; float s = di * di;
    float4 h  = *(const float4*)&hw32[(size_t)v * LAT + c4];
    float4 l  = *(const float4*)&g_lat[(size_t)v * LAT + c4];
    float4 b0 = *(const float4*)&bl[c4];
    float4 b1 = *(const float4*)&bs[c4];
    float4 b2 = *(const float4*)&bs[LAT + c4];
    float4 b3 = *(const float4*)&bs[2 * LAT + c4];
    float4 r;
    r.x = l.x + h.x * s + b0.x + b1.x + b2.x + b3.x;
    r.y = l.y + h.y * s + b0.y + b1.y + b2.y + b3.y;
    r.z = l.z + h.z * s + b0.z + b1.z + b2.z + b3.z;
    r.w = l.w + h.w * s + b0.w + b1.w + b2.w + b3.w;
    *(float4*)&out[(size_t)v * LAT + c4] = r;
}

// ---------------- edge scatters (vector L2 reductions) ----------------
// width 64: 16 threads per edge, one red.v4 each
__global__ __launch_bounds__(256) void k_scatter64(const float* __restrict__ hw,
                                                   const int* __restrict__ src,
                                                   const int* __restrict__ dst,
                                                   float* __restrict__ acc) {
    int t = blockIdx.x * blockDim.x + threadIdx.x;     // Ee*16 threads
    int e = t >> 4;
    int c4 = (t & 15) * 4;
    int s = src[e], d = dst[e];
    float nm = g_norm[e];
    float4 v = *(const float4*)&hw[(size_t)s * HID + c4];
    red4(&acc[(size_t)d * HID + c4], v.x * nm, v.y * nm, v.z * nm, v.w * nm);
}

// width 32: 8 threads per edge
__global__ __launch_bounds__(256) void k_scatter32(const float* __restrict__ hw32,
                                                   const int* __restrict__ src,
                                                   const int* __restrict__ dst,
                                                   float* __restrict__ out) {
    int t = blockIdx.x * blockDim.x + threadIdx.x;     // Ee*8 threads
    int e = t >> 3;
    int c4 = (t & 7) * 4;
    int s = src[e], d = dst[e];
    float nm = g_norm[e];
    float4 v = *(const float4*)&hw32[(size_t)s * LAT + c4];
    red4(&out[(size_t)d * LAT + c4], v.x * nm, v.y * nm, v.z * nm, v.w * nm);
}

// ---------------- launch ----------------
extern "C" void kernel_launch(void* const* d_in, const int* in_sizes, int n_in,
                              void* d_out, int out_size)
{
    const float* x    = (const float*)d_in[0];
    const int*   ei   = (const int*)  d_in[1];
    const float* W_in = (const float*)d_in[2];
    const float* b_in = (const float*)d_in[3];
    const float* Wg   = (const float*)d_in[4];
    const float* bg   = (const float*)d_in[5];
    const float* Ws   = (const float*)d_in[6];
    const float* bs   = (const float*)d_in[7];
    const float* Wl   = (const float*)d_in[8];
    const float* bl   = (const float*)d_in[9];
    float*       out  = (float*)d_out;

    const int* src = ei;
    const int* dst = ei + Ee;

    float* p_dinv; cudaGetSymbolAddress((void**)&p_dinv, g_dinv);
    float* p_h;    cudaGetSymbolAddress((void**)&p_h,    g_h);
    float* p_hw;   cudaGetSymbolAddress((void**)&p_hw,   g_hw);
    float* p_acc;  cudaGetSymbolAddress((void**)&p_acc,  g_acc);
    float* p_lat;  cudaGetSymbolAddress((void**)&p_lat,  g_lat);

    // degrees + per-edge norms (reused by all 4 aggregation passes)
    k_deg_init <<<(Nn + 255) / 256, 256>>>();
    k_deg_count<<<(Ee + 255) / 256, 256>>>(dst);
    k_dinv     <<<(Nn + 255) / 256, 256>>>();
    k_norm     <<<(Ee + 255) / 256, 256>>>(src, dst);

    // h0 = x @ W_in + b_in        K=128, COLS=64, R=32, no pad (48KB smem fit)
    k_gemm<128, 64, 32, 128, false, true, false>
        <<<(Nn + 31) / 32, 256>>>(x, W_in, b_in, p_h, Nn);

    for (int i = 0; i < 3; i++) {
        const float* hin = (i == 0) ? p_h : p_acc;
        // latent skip: g_lat (=, then +=) f(h) @ Ws[i]
        if (i == 0)
            k_gemm<64, 32, 128, 65, false, false, false>
                <<<(Nn + 127) / 128, 256>>>(hin, Ws, nullptr, p_lat, Nn);
        else if (i == 1)
            k_gemm<64, 32, 128, 65, true, false, true>
                <<<(Nn + 127) / 128, 256>>>(hin, Ws + 1 * HID * LAT, nullptr, p_lat, Nn);
        else
            k_gemm<64, 32, 128, 65, true, false, true>
                <<<(Nn + 127) / 128, 256>>>(hin, Ws + 2 * HID * LAT, nullptr, p_lat, Nn);

        // hw = f(h) @ Wg[i]
        if (i == 0)
            k_gemm<64, 64, 64, 65, false, false, false>
                <<<(Nn + 63) / 64, 256>>>(hin, Wg, nullptr, p_hw, Nn);
        else
            k_gemm<64, 64, 64, 65, true, false, false>
                <<<(Nn + 63) / 64, 256>>>(hin, Wg + (size_t)i * HID * HID, nullptr, p_hw, Nn);

        // acc = bg[i] + hw * dinv^2  (bias + self-loop), then edge scatter
        k_init_acc<<<Nn * 16 / 256, 256>>>(p_hw, bg + i * HID);
        k_scatter64<<<Ee * 16 / 256, 256>>>(p_hw, src, dst, p_acc);
    }

    // hw32 = leaky(acc3) @ Wl   (GEMM before aggregation -> width-32 scatter)
    k_gemm<64, 32, 128, 65, true, false, false>
        <<<(Nn + 127) / 128, 256>>>(p_acc, Wl, nullptr, p_hw, Nn);

    // out = lat + hw32*dinv^2 + (bl + sum bs), then final edge scatter into out
    k_out_init<<<Nn * 8 / 256, 256>>>(p_hw, bl, bs, out);
    k_scatter32<<<Ee * 8 / 256, 256>>>(p_hw, src, dst, out);
}

// round 2
// speedup vs baseline: 1.3935x; 1.3935x over previous
#include <cuda_runtime.h>
#include <cstdint>

// Problem constants (fixed by the reference setup_inputs)
static constexpr int Nn   = 100000;   // nodes
static constexpr int Ee   = 1600000;  // directed edges
static constexpr int HID  = 64;
static constexpr int LAT  = 32;

static constexpr int SCAN_BLOCKS = (Nn + 255) / 256;   // 391

// ---------------- device scratch (no allocations allowed) ----------------
__device__ __align__(16) float g_dinv[Nn];
__device__ int                 g_degi[Nn];
__device__ int                 g_incl[Nn];        // block-local inclusive scan
__device__ int                 g_boff[SCAN_BLOCKS]; // exclusive block offsets
__device__ int                 g_rs  [Nn + 1];    // CSR row_start
__device__ int                 g_cur [Nn];        // fill cursors
__device__ int                 g_csrc[Ee];        // CSR src indices (grouped by dst)
__device__ __align__(16) float g_cnrm[Ee];        // CSR per-edge norm
__device__ __align__(16) float g_h  [(size_t)Nn * HID];
__device__ __align__(16) float g_hw [(size_t)Nn * HID];  // also reused at width 32
__device__ __align__(16) float g_acc[(size_t)Nn * HID];
__device__ __align__(16) float g_lat[(size_t)Nn * LAT];

// ---------------- helpers ----------------
__device__ __forceinline__ float leaky(float v) { return v > 0.f ? v : 0.2f * v; }

// ---------------- degree / dinv ----------------
__global__ void k_deg_init() {
    int i = blockIdx.x * blockDim.x + threadIdx.x;
    if (i < Nn) g_degi[i] = 1;  // self loop
}
__global__ void k_deg_count(const int* __restrict__ dst) {
    int e = blockIdx.x * blockDim.x + threadIdx.x;
    if (e < Ee) atomicAdd(&g_degi[dst[e]], 1);
}
__global__ void k_dinv() {
    int i = blockIdx.x * blockDim.x + threadIdx.x;
    if (i < Nn) g_dinv[i] = rsqrtf((float)g_degi[i]);
}

// ---------------- prefix scan of in-degrees (3 kernels) ----------------
__global__ void k_scan1() {
    __shared__ int sh[256];
    int i = blockIdx.x * 256 + threadIdx.x;
    int v = (i < Nn) ? (g_degi[i] - 1) : 0;
    sh[threadIdx.x] = v;
    __syncthreads();
    #pragma unroll
    for (int off = 1; off < 256; off <<= 1) {
        int t = (threadIdx.x >= off) ? sh[threadIdx.x - off] : 0;
        __syncthreads();
        sh[threadIdx.x] += t;
        __syncthreads();
    }
    if (i < Nn) g_incl[i] = sh[threadIdx.x];
    if (threadIdx.x == 255) g_boff[blockIdx.x] = sh[255];  // block total (scanned next)
}
__global__ void k_scan2() {
    __shared__ int sh[512];
    int t = threadIdx.x;
    int v = (t < SCAN_BLOCKS) ? g_boff[t] : 0;
    sh[t] = v;
    __syncthreads();
    #pragma unroll
    for (int off = 1; off < 512; off <<= 1) {
        int u = (t >= off) ? sh[t - off] : 0;
        __syncthreads();
        sh[t] += u;
        __syncthreads();
    }
    if (t < SCAN_BLOCKS) g_boff[t] = sh[t] - v;  // exclusive
}
__global__ void k_scan3() {
    int i = blockIdx.x * 256 + threadIdx.x;
    if (i < Nn) {
        int val = g_degi[i] - 1;
        int start = g_boff[i >> 8] + g_incl[i] - val;   // exclusive
        g_rs[i]  = start;
        g_cur[i] = 0;
        if (i == Nn - 1) g_rs[Nn] = start + val;
    }
}
__global__ void k_fill(const int* __restrict__ src, const int* __restrict__ dst) {
    int e = blockIdx.x * blockDim.x + threadIdx.x;
    if (e < Ee) {
        int s = src[e], d = dst[e];
        int pos = g_rs[d] + atomicAdd(&g_cur[d], 1);
        g_csrc[pos] = s;
        g_cnrm[pos] = g_dinv[s] * g_dinv[d];
    }
}

// ---------------- tiled fp32 GEMM: out[N,COLS] = f(H)[N,K] @ W[K,COLS] (+bias) (+=) ----
template<int K, int COLS, int R, int PADK, bool LEAKY, bool ADD_BIAS, bool ACCUM>
__global__ __launch_bounds__(256) void k_gemm(const float* __restrict__ H,
                                              const float* __restrict__ W,
                                              const float* __restrict__ bias,
                                              float* __restrict__ out, int nrows)
{
    constexpr int CG     = COLS / 4;
    constexpr int GROUPS = 256 / CG;
    constexpr int RPT    = R / GROUPS;
    __shared__ float Hs[R * PADK];
    __shared__ float Wsh[K * COLS];

    const int tid  = threadIdx.x;
    const int row0 = blockIdx.x * R;

    constexpr int NV = R * K / 4;
    #pragma unroll
    for (int i = tid; i < NV; i += 256) {
        int r  = i / (K / 4);
        int k4 = i % (K / 4);
        float4 v = make_float4(0.f, 0.f, 0.f, 0.f);
        if (row0 + r < nrows)
            v = *(const float4*)(H + (size_t)(row0 + r) * K + k4 * 4);
        if (LEAKY) { v.x = leaky(v.x); v.y = leaky(v.y); v.z = leaky(v.z); v.w = leaky(v.w); }
        float* dp = &Hs[r * PADK + k4 * 4];
        if (PADK % 4 == 0) { *(float4*)dp = v; }
        else { dp[0] = v.x; dp[1] = v.y; dp[2] = v.z; dp[3] = v.w; }
    }
    #pragma unroll
    for (int i = tid; i < K * COLS / 4; i += 256)
        *(float4*)&Wsh[i * 4] = *(const float4*)(W + i * 4);
    __syncthreads();

    const int cg    = tid % CG;
    const int rbase = (tid / CG) * RPT;

    float acc[RPT][4];
    #pragma unroll
    for (int i = 0; i < RPT; i++) { acc[i][0] = acc[i][1] = acc[i][2] = acc[i][3] = 0.f; }

    #pragma unroll 8
    for (int k = 0; k < K; k++) {
        float4 w = *(float4*)&Wsh[k * COLS + cg * 4];
        #pragma unroll
        for (int i = 0; i < RPT; i++) {
            float a = Hs[(rbase + i) * PADK + k];
            acc[i][0] += a * w.x; acc[i][1] += a * w.y;
            acc[i][2] += a * w.z; acc[i][3] += a * w.w;
        }
    }

    float4 b = make_float4(0.f, 0.f, 0.f, 0.f);
    if (ADD_BIAS) b = *(const float4*)(bias + cg * 4);
    #pragma unroll
    for (int i = 0; i < RPT; i++) {
        int r = row0 + rbase + i;
        if (r < nrows) {
            float4 res = make_float4(acc[i][0] + b.x, acc[i][1] + b.y,
                                     acc[i][2] + b.z, acc[i][3] + b.w);
            float* op = out + (size_t)r * COLS + cg * 4;
            if (ACCUM) {
                float4 o = *(float4*)op;
                res.x += o.x; res.y += o.y; res.z += o.z; res.w += o.w;
            }
            *(float4*)op = res;
        }
    }
}

// ---------------- CSR aggregation (warp per node) ----------------
// width 64: lane owns float2. out[v] = bg + hw[v]*dinv^2 + sum_e norm*hw[src]
__global__ __launch_bounds__(256) void k_agg64(const float* __restrict__ hw,
                                               const float* __restrict__ bg,
                                               float* __restrict__ out)
{
    int w = (blockIdx.x * blockDim.x + threadIdx.x) >> 5;
    int lane = threadIdx.x & 31;
    if (w >= Nn) return;
    const int c = lane * 2;
    float di = g_dinv[w];
    float s  = di * di;
    float2 hv = *(const float2*)&hw[(size_t)w * HID + c];
    float2 a;
    a.x = bg[c]     + hv.x * s;
    a.y = bg[c + 1] + hv.y * s;

    int j   = g_rs[w];
    int end = g_rs[w + 1];
    for (; j + 2 <= end; j += 2) {
        int   s0 = g_csrc[j],     s1 = g_csrc[j + 1];
        float n0 = g_cnrm[j],     n1 = g_cnrm[j + 1];
        float2 h0 = *(const float2*)&hw[(size_t)s0 * HID + c];
        float2 h1 = *(const float2*)&hw[(size_t)s1 * HID + c];
        a.x += n0 * h0.x + n1 * h1.x;
        a.y += n0 * h0.y + n1 * h1.y;
    }
    if (j < end) {
        int   s0 = g_csrc[j];
        float n0 = g_cnrm[j];
        float2 h0 = *(const float2*)&hw[(size_t)s0 * HID + c];
        a.x += n0 * h0.x;
        a.y += n0 * h0.y;
    }
    *(float2*)&out[(size_t)w * HID + c] = a;
}

// width 32: lane owns 1 col. out[v] = lat[v] + (bl+Σbs) + hw32[v]*dinv^2 + Σ norm*hw32[src]
__global__ __launch_bounds__(256) void k_agg32(const float* __restrict__ hw32,
                                               const float* __restrict__ bl,
                                               const float* __restrict__ bs,
                                               float* __restrict__ out)
{
    int w = (blockIdx.x * blockDim.x + threadIdx.x) >> 5;
    int lane = threadIdx.x & 31;
    if (w >= Nn) return;
    float di = g_dinv[w];
    float s  = di * di;
    float a = g_lat[(size_t)w * LAT + lane]
            + bl[lane] + bs[lane] + bs[LAT + lane] + bs[2 * LAT + lane]
            + hw32[(size_t)w * LAT + lane] * s;

    int j   = g_rs[w];
    int end = g_rs[w + 1];
    for (; j + 2 <= end; j += 2) {
        int   s0 = g_csrc[j],  s1 = g_csrc[j + 1];
        float n0 = g_cnrm[j],  n1 = g_cnrm[j + 1];
        float h0 = hw32[(size_t)s0 * LAT + lane];
        float h1 = hw32[(size_t)s1 * LAT + lane];
        a += n0 * h0 + n1 * h1;
    }
    if (j < end)
        a += g_cnrm[j] * hw32[(size_t)g_csrc[j] * LAT + lane];

    out[(size_t)w * LAT + lane] = a;
}

// ---------------- launch ----------------
extern "C" void kernel_launch(void* const* d_in, const int* in_sizes, int n_in,
                              void* d_out, int out_size)
{
    const float* x    = (const float*)d_in[0];
    const int*   ei   = (const int*)  d_in[1];
    const float* W_in = (const float*)d_in[2];
    const float* b_in = (const float*)d_in[3];
    const float* Wg   = (const float*)d_in[4];
    const float* bg   = (const float*)d_in[5];
    const float* Ws   = (const float*)d_in[6];
    const float* bs   = (const float*)d_in[7];
    const float* Wl   = (const float*)d_in[8];
    const float* bl   = (const float*)d_in[9];
    float*       out  = (float*)d_out;

    const int* src = ei;
    const int* dst = ei + Ee;

    float* p_h;    cudaGetSymbolAddress((void**)&p_h,    g_h);
    float* p_hw;   cudaGetSymbolAddress((void**)&p_hw,   g_hw);
    float* p_acc;  cudaGetSymbolAddress((void**)&p_acc,  g_acc);
    float* p_lat;  cudaGetSymbolAddress((void**)&p_lat,  g_lat);

    // ---- CSR build: degrees -> dinv -> prefix scan -> fill (norms in CSR order)
    k_deg_init <<<(Nn + 255) / 256, 256>>>();
    k_deg_count<<<(Ee + 255) / 256, 256>>>(dst);
    k_dinv     <<<(Nn + 255) / 256, 256>>>();
    k_scan1    <<<SCAN_BLOCKS, 256>>>();
    k_scan2    <<<1, 512>>>();
    k_scan3    <<<SCAN_BLOCKS, 256>>>();
    k_fill     <<<(Ee + 255) / 256, 256>>>(src, dst);

    // h0 = x @ W_in + b_in
    k_gemm<128, 64, 32, 128, false, true, false>
        <<<(Nn + 31) / 32, 256>>>(x, W_in, b_in, p_h, Nn);

    const int AGG_GRID = (Nn * 32 + 255) / 256;

    for (int i = 0; i < 3; i++) {
        const float* hin = (i == 0) ? p_h : p_acc;
        // latent skip: g_lat (=, then +=) f(h) @ Ws[i]
        if (i == 0)
            k_gemm<64, 32, 128, 65, false, false, false>
                <<<(Nn + 127) / 128, 256>>>(hin, Ws, nullptr, p_lat, Nn);
        else if (i == 1)
            k_gemm<64, 32, 128, 65, true, false, true>
                <<<(Nn + 127) / 128, 256>>>(hin, Ws + 1 * HID * LAT, nullptr, p_lat, Nn);
        else
            k_gemm<64, 32, 128, 65, true, false, true>
                <<<(Nn + 127) / 128, 256>>>(hin, Ws + 2 * HID * LAT, nullptr, p_lat, Nn);

        // hw = f(h) @ Wg[i]
        if (i == 0)
            k_gemm<64, 64, 64, 65, false, false, false>
                <<<(Nn + 63) / 64, 256>>>(hin, Wg, nullptr, p_hw, Nn);
        else
            k_gemm<64, 64, 64, 65, true, false, false>
                <<<(Nn + 63) / 64, 256>>>(hin, Wg + (size_t)i * HID * HID, nullptr, p_hw, Nn);

        // acc = bg[i] + hw*dinv^2 + CSR-gathered neighbor sum (no atomics)
        k_agg64<<<AGG_GRID, 256>>>(p_hw, bg + i * HID, p_acc);
    }

    // hw32 = leaky(acc3) @ Wl (GEMM before aggregation -> width-32 gather)
    k_gemm<64, 32, 128, 65, true, false, false>
        <<<(Nn + 127) / 128, 256>>>(p_acc, Wl, nullptr, p_hw, Nn);

    // out = lat + (bl+Σbs) + hw32*dinv^2 + CSR-gathered neighbor sum
    k_agg32<<<AGG_GRID, 256>>>(p_hw, bl, bs, out);
}